// round 1
// baseline (speedup 1.0000x reference)
#include <cuda_runtime.h>
#include <math.h>

// Problem dims
#define BB 4
#define TT 3072
#define DD 1024
#define HH 16
#define HD 64
#define TC 1024          // conv outputs per batch
#define TKK 1025         // k_tmp rows per batch

// ---------------- static scratch (no allocations allowed) ----------------
__device__ float g_wc[DD * 3 * DD];            // repacked conv weight [o][kw*1024+i]  (12 MB)
__device__ float g_ktmp[BB * TKK * DD];        // k_tmp  (16.8 MB)
__device__ float g_q[BB * TT * DD];            // Q      (48 MB)
__device__ float g_k[BB * TKK * DD];           // K      (16.8 MB)
__device__ float g_v[BB * TKK * DD];           // V      (16.8 MB)
__device__ float g_o[BB * TT * DD];            // attn out (48 MB)

// ---------------- repack Wconv (o,i,kw) -> (o, kw*1024+i) ----------------
__global__ void repack_conv_kernel(const float* __restrict__ Wconv) {
    int idx = blockIdx.x * blockDim.x + threadIdx.x;
    if (idx >= DD * DD * 3) return;
    int o  = idx / (DD * 3);
    int r2 = idx % (DD * 3);
    int i  = r2 / 3;
    int kw = r2 % 3;
    g_wc[(long)o * (3 * DD) + kw * DD + i] = Wconv[idx];
}

// ---------------- copy x[:,0,:] into k_tmp row 0 per batch ----------------
__global__ void copy_row0_kernel(const float* __restrict__ x) {
    int idx = blockIdx.x * blockDim.x + threadIdx.x;   // 0 .. 4*1024-1
    if (idx >= BB * DD) return;
    int b = idx / DD, i = idx % DD;
    g_ktmp[(long)b * TKK * DD + i] = x[(long)b * TT * DD + i];
}

// ---------------- generic SGEMM: C[M,N] = A(M,K; row stride lda) @ W[N,K]^T (+bias)
// outmap==1: conv output row r -> k_tmp row (r + r/1024 + 1)   (ldc == N == 1024)
#define GBM 128
#define GBN 128
#define GBK 8
__global__ void __launch_bounds__(256, 2)
sgemm_kernel(const float* __restrict__ A, long lda,
             const float* __restrict__ W,
             const float* __restrict__ bias,
             float* __restrict__ C,
             int M, int N, int K, int outmap)
{
    __shared__ float As[GBK][GBM];
    __shared__ float Ws[GBK][GBN];

    const int tid = threadIdx.x;
    const int bm  = blockIdx.y * GBM;
    const int bn  = blockIdx.x * GBN;
    const int lr  = tid >> 1;          // 0..127
    const int lc  = (tid & 1) * 4;     // 0 or 4
    const int tx  = tid & 15;
    const int ty  = tid >> 4;

    float acc[8][8];
#pragma unroll
    for (int i = 0; i < 8; i++)
#pragma unroll
        for (int j = 0; j < 8; j++) acc[i][j] = 0.f;

    const bool aval = (bm + lr) < M;
    const bool wval = (bn + lr) < N;
    const float* Aptr = A + (long)(bm + lr) * lda + lc;
    const float* Wptr = W + (long)(bn + lr) * K + lc;

    for (int k0 = 0; k0 < K; k0 += GBK) {
        float4 av = aval ? *(const float4*)(Aptr + k0) : make_float4(0.f, 0.f, 0.f, 0.f);
        float4 wv = wval ? *(const float4*)(Wptr + k0) : make_float4(0.f, 0.f, 0.f, 0.f);
        As[lc + 0][lr] = av.x; As[lc + 1][lr] = av.y; As[lc + 2][lr] = av.z; As[lc + 3][lr] = av.w;
        Ws[lc + 0][lr] = wv.x; Ws[lc + 1][lr] = wv.y; Ws[lc + 2][lr] = wv.z; Ws[lc + 3][lr] = wv.w;
        __syncthreads();
#pragma unroll
        for (int kk = 0; kk < GBK; kk++) {
            float a[8], w[8];
#pragma unroll
            for (int i = 0; i < 8; i++) a[i] = As[kk][ty * 8 + i];
#pragma unroll
            for (int j = 0; j < 8; j++) w[j] = Ws[kk][tx * 8 + j];
#pragma unroll
            for (int i = 0; i < 8; i++)
#pragma unroll
                for (int j = 0; j < 8; j++) acc[i][j] = fmaf(a[i], w[j], acc[i][j]);
        }
        __syncthreads();
    }

#pragma unroll
    for (int i = 0; i < 8; i++) {
        int row = bm + ty * 8 + i;
        if (row >= M) continue;
        long crow = row;
        if (outmap == 1) crow = (long)row + row / TC + 1;   // scatter into k_tmp
        float* Cp = C + crow * N;
#pragma unroll
        for (int j = 0; j < 8; j += 4) {
            int col = bn + tx * 8 + j;
            float4 v;
            v.x = acc[i][j + 0] + (bias ? bias[col + 0] : 0.f);
            v.y = acc[i][j + 1] + (bias ? bias[col + 1] : 0.f);
            v.z = acc[i][j + 2] + (bias ? bias[col + 2] : 0.f);
            v.w = acc[i][j + 3] + (bias ? bias[col + 3] : 0.f);
            *(float4*)(Cp + col) = v;
        }
    }
}

// ---------------- flash attention with 3k<=q mask ----------------
// 128 queries/block, 1 query per thread, key tiles of 32.
#define AT_BQ 128
#define AT_BK 32
__global__ void __launch_bounds__(128, 2)
attn_kernel(const float* __restrict__ Q, const float* __restrict__ Kg,
            const float* __restrict__ Vg, float* __restrict__ O)
{
    __shared__ float Ks[AT_BK][HD];
    __shared__ float Vs[AT_BK][HD];

    const int bh = blockIdx.y;
    const int b  = bh >> 4;
    const int h  = bh & 15;
    const int q0 = blockIdx.x * AT_BQ;
    const int tid = threadIdx.x;
    const int q  = q0 + tid;
    const float scale = 0.125f;   // 1/sqrt(64)

    float qreg[HD];
    const float* qp = Q + ((long)(b * TT + q) * DD) + h * HD;
#pragma unroll
    for (int i = 0; i < HD; i += 4) {
        float4 v = *(const float4*)(qp + i);
        qreg[i] = v.x * scale; qreg[i + 1] = v.y * scale;
        qreg[i + 2] = v.z * scale; qreg[i + 3] = v.w * scale;
    }

    float o[HD];
#pragma unroll
    for (int i = 0; i < HD; i++) o[i] = 0.f;
    float m = -1e30f, l = 0.f;

    const int kallow = q / 3;                       // max allowed key idx for this query
    const int nk = ((q0 + AT_BQ - 1) / 3) + 1;      // keys needed by the whole block

    for (int kt = 0; kt < nk; kt += AT_BK) {
        // cooperative tile load: AT_BK x 64 floats each for K and V
        for (int idx = tid; idx < AT_BK * (HD / 4); idx += AT_BQ) {
            int r  = idx >> 4;            // HD/4 = 16 float4 per row
            int c4 = (idx & 15) * 4;
            int kid = kt + r;
            float4 kv = make_float4(0.f, 0.f, 0.f, 0.f), vv = kv;
            if (kid < TKK) {
                long off = ((long)(b * TKK + kid) * DD) + h * HD + c4;
                kv = *(const float4*)(Kg + off);
                vv = *(const float4*)(Vg + off);
            }
            *(float4*)&Ks[r][c4] = kv;
            *(float4*)&Vs[r][c4] = vv;
        }
        __syncthreads();

        float s[AT_BK];
#pragma unroll
        for (int j = 0; j < AT_BK; j++) {
            float acc = 0.f;
#pragma unroll
            for (int i = 0; i < HD; i++) acc = fmaf(qreg[i], Ks[j][i], acc);
            s[j] = acc;
        }

        float mnew = m;
#pragma unroll
        for (int j = 0; j < AT_BK; j++) {
            if (kt + j > kallow) s[j] = -1e30f;
            mnew = fmaxf(mnew, s[j]);
        }

        float corr = __expf(m - mnew);
        l *= corr;
#pragma unroll
        for (int i = 0; i < HD; i++) o[i] *= corr;

#pragma unroll
        for (int j = 0; j < AT_BK; j++) {
            float p = __expf(s[j] - mnew);
            l += p;
#pragma unroll
            for (int i = 0; i < HD; i++) o[i] = fmaf(p, Vs[j][i], o[i]);
        }
        m = mnew;
        __syncthreads();
    }

    float inv = 1.f / l;
    float* op = O + ((long)(b * TT + q) * DD) + h * HD;
#pragma unroll
    for (int i = 0; i < HD; i += 4) {
        float4 v;
        v.x = o[i] * inv; v.y = o[i + 1] * inv;
        v.z = o[i + 2] * inv; v.w = o[i + 3] * inv;
        *(float4*)(op + i) = v;
    }
}

// ---------------- launch ----------------
extern "C" void kernel_launch(void* const* d_in, const int* in_sizes, int n_in,
                              void* d_out, int out_size)
{
    const float* x     = (const float*)d_in[0];
    const float* Wq    = (const float*)d_in[1];
    const float* Wk    = (const float*)d_in[2];
    const float* Wv    = (const float*)d_in[3];
    const float* Wo    = (const float*)d_in[4];
    const float* bo    = (const float*)d_in[5];
    const float* Wconv = (const float*)d_in[6];
    float* out = (float*)d_out;

    float* wc   = nullptr; cudaGetSymbolAddress((void**)&wc,   g_wc);
    float* ktmp = nullptr; cudaGetSymbolAddress((void**)&ktmp, g_ktmp);
    float* qb   = nullptr; cudaGetSymbolAddress((void**)&qb,   g_q);
    float* kb   = nullptr; cudaGetSymbolAddress((void**)&kb,   g_k);
    float* vb   = nullptr; cudaGetSymbolAddress((void**)&vb,   g_v);
    float* ob   = nullptr; cudaGetSymbolAddress((void**)&ob,   g_o);

    // 1. repack conv weight
    {
        int n = DD * DD * 3;
        repack_conv_kernel<<<(n + 255) / 256, 256>>>(Wconv);
    }
    // 2. k_tmp row 0 = x[:,0,:]
    {
        int n = BB * DD;
        copy_row0_kernel<<<(n + 255) / 256, 256>>>(x);
    }
    // 3. conv-as-GEMM:  kc = (x viewed with lda=3*D) @ g_wc^T  -> scattered into k_tmp
    {
        dim3 grid(DD / GBN, (BB * TC + GBM - 1) / GBM);   // (8, 32)
        sgemm_kernel<<<grid, 256>>>(x, 3L * DD, wc, nullptr, ktmp, BB * TC, DD, 3 * DD, 1);
    }
    // 4. Q = x @ Wq^T
    {
        dim3 grid(DD / GBN, (BB * TT + GBM - 1) / GBM);   // (8, 96)
        sgemm_kernel<<<grid, 256>>>(x, (long)DD, Wq, nullptr, qb, BB * TT, DD, DD, 0);
    }
    // 5/6. K,V = k_tmp @ Wk^T / Wv^T
    {
        dim3 grid(DD / GBN, (BB * TKK + GBM - 1) / GBM);  // (8, 33)
        sgemm_kernel<<<grid, 256>>>(ktmp, (long)DD, Wk, nullptr, kb, BB * TKK, DD, DD, 0);
        sgemm_kernel<<<grid, 256>>>(ktmp, (long)DD, Wv, nullptr, vb, BB * TKK, DD, DD, 0);
    }
    // 7. attention
    {
        dim3 grid(TT / AT_BQ, BB * HH);                   // (24, 64)
        attn_kernel<<<grid, AT_BQ>>>(qb, kb, vb, ob);
    }
    // 8. out = o @ Wo^T + bo
    {
        dim3 grid(DD / GBN, (BB * TT + GBM - 1) / GBM);   // (8, 96)
        sgemm_kernel<<<grid, 256>>>(ob, (long)DD, Wo, bo, out, BB * TT, DD, DD, 0);
    }
}

// round 7
// speedup vs baseline: 1.6064x; 1.6064x over previous
#include <cuda_runtime.h>
#include <cuda_bf16.h>
#include <cstdint>
#include <math.h>

// Problem dims
#define BB 4
#define TT 3072
#define DD 1024
#define HH 16
#define HD 64
#define TC 1024          // conv outputs per batch
#define TKK 1025         // k_tmp rows per batch

// ---------------- static scratch ----------------
__device__ __nv_bfloat16 g_xhi[BB * TT * DD], g_xlo[BB * TT * DD];
__device__ __nv_bfloat16 g_wqhi[DD * DD], g_wqlo[DD * DD];
__device__ __nv_bfloat16 g_wkhi[DD * DD], g_wklo[DD * DD];
__device__ __nv_bfloat16 g_wvhi[DD * DD], g_wvlo[DD * DD];
__device__ __nv_bfloat16 g_wohi[DD * DD], g_wolo[DD * DD];
__device__ __nv_bfloat16 g_wchi[DD * 3 * DD], g_wclo[DD * 3 * DD];
__device__ __nv_bfloat16 g_khi2[BB * TKK * DD], g_klo2[BB * TKK * DD];  // k_tmp hi/lo
__device__ float g_q[BB * TT * DD];
__device__ float g_k[BB * TKK * DD];
__device__ float g_v[BB * TKK * DD];
__device__ __nv_bfloat16 g_ohi[BB * TT * DD], g_olo[BB * TT * DD];

// ---------------- helpers ----------------
__device__ __forceinline__ uint32_t smem_u32(const void* p) {
    uint32_t a;
    asm("{ .reg .u64 t; cvta.to.shared.u64 t, %1; cvt.u32.u64 %0, t; }" : "=r"(a) : "l"(p));
    return a;
}
__device__ __forceinline__ void ldsm4(uint32_t* r, uint32_t addr) {
    asm volatile("ldmatrix.sync.aligned.m8n8.x4.shared.b16 {%0,%1,%2,%3}, [%4];"
        : "=r"(r[0]), "=r"(r[1]), "=r"(r[2]), "=r"(r[3]) : "r"(addr));
}
__device__ __forceinline__ void mma16816(float* c, const uint32_t* a, uint32_t b0, uint32_t b1) {
    asm volatile("mma.sync.aligned.m16n8k16.row.col.f32.bf16.bf16.f32 "
        "{%0,%1,%2,%3}, {%4,%5,%6,%7}, {%8,%9}, {%0,%1,%2,%3};"
        : "+f"(c[0]), "+f"(c[1]), "+f"(c[2]), "+f"(c[3])
        : "r"(a[0]), "r"(a[1]), "r"(a[2]), "r"(a[3]), "r"(b0), "r"(b1));
}

// ---------------- split / repack kernels ----------------
__global__ void split_kernel(const float* __restrict__ s, __nv_bfloat16* __restrict__ hi,
                             __nv_bfloat16* __restrict__ lo, int n) {
    int i = blockIdx.x * 256 + threadIdx.x;
    if (i >= n) return;
    float v = s[i];
    __nv_bfloat16 h = __float2bfloat16(v);
    hi[i] = h;
    lo[i] = __float2bfloat16(v - __bfloat162float(h));
}
__global__ void repack_conv_kernel(const float* __restrict__ W, __nv_bfloat16* __restrict__ hi,
                                   __nv_bfloat16* __restrict__ lo) {
    int idx = blockIdx.x * 256 + threadIdx.x;
    if (idx >= DD * DD * 3) return;
    int o = idx / (DD * 3);
    int r = idx % (DD * 3);
    int i = r / 3, kw = r % 3;
    float v = W[idx];
    __nv_bfloat16 h = __float2bfloat16(v);
    long d = (long)o * (3 * DD) + kw * DD + i;
    hi[d] = h;
    lo[d] = __float2bfloat16(v - __bfloat162float(h));
}
__global__ void copy_row0_kernel(const float* __restrict__ x, __nv_bfloat16* __restrict__ khi,
                                 __nv_bfloat16* __restrict__ klo) {
    int idx = blockIdx.x * 256 + threadIdx.x;
    if (idx >= BB * DD) return;
    int b = idx / DD, i = idx % DD;
    float v = x[(long)b * TT * DD + i];
    __nv_bfloat16 h = __float2bfloat16(v);
    long d = (long)b * TKK * DD + i;
    khi[d] = h;
    klo[d] = __float2bfloat16(v - __bfloat162float(h));
}

// ---------------- mma.sync GEMM: C[M,1024] = A @ B^T (bf16x3 split) ----------------
// A: [M,K] hi/lo bf16 (row stride lda); B: [1024,K] hi/lo bf16.
// outmap 0: fp32 Cf (+bias).  outmap 1: conv scatter -> bf16 hi/lo pair.
// smem stage: 4 tiles (Ahi, Alo, Bhi, Blo), each 128 rows x 80B (64B data + 16B pad)
#define GM_BM 128
#define GM_BN 128
#define GM_BK 32
#define GM_ROWB 80
#define GM_TILE (128 * GM_ROWB)        // 10240
#define GM_STAGE (4 * GM_TILE)         // 40960
#define GM_SMEM (2 * GM_STAGE)         // 81920

__global__ void __launch_bounds__(256)
gemm_mma(const __nv_bfloat16* __restrict__ Ahi, const __nv_bfloat16* __restrict__ Alo, long lda,
         const __nv_bfloat16* __restrict__ Bhi, const __nv_bfloat16* __restrict__ Blo,
         const float* __restrict__ bias,
         float* __restrict__ Cf, __nv_bfloat16* __restrict__ Chi, __nv_bfloat16* __restrict__ Clo,
         int M, int K, int outmap)
{
    extern __shared__ char smem[];
    const uint32_t sb = smem_u32(smem);
    const int tid = threadIdx.x;
    const int wid = tid >> 5, lane = tid & 31;
    const int bm = blockIdx.y * GM_BM, bn = blockIdx.x * GM_BN;
    const int mbase = (wid & 3) * 32;
    const int nbase = (wid >> 2) * 64;

    const int grp = lane >> 3, rowg = lane & 7;
    const int a_row = (grp & 1) * 8 + rowg;
    const int a_koff = (grp >> 1) * 16;
    const int b_row = (grp >> 1) * 8 + rowg;
    const int b_koff = (grp & 1) * 16;

    float acc[2][8][4];
#pragma unroll
    for (int i = 0; i < 2; i++)
#pragma unroll
        for (int j = 0; j < 8; j++)
#pragma unroll
            for (int k = 0; k < 4; k++) acc[i][j][k] = 0.f;

    auto load_stage = [&](int stg, int c) {
        char* base = smem + stg * GM_STAGE;
        const int k0 = c * GM_BK;
#pragma unroll
        for (int it = 0; it < 8; it++) {
            int i = it * 256 + tid;
            int t = i >> 9;               // 0 Ahi, 1 Alo, 2 Bhi, 3 Blo
            int r = (i >> 2) & 127;
            int s = i & 3;
            uint4 v = make_uint4(0, 0, 0, 0);
            if (t < 2) {
                int row = bm + r;
                if (row < M) {
                    const __nv_bfloat16* src = t ? Alo : Ahi;
                    v = *(const uint4*)(src + (long)row * lda + k0 + s * 8);
                }
            } else {
                const __nv_bfloat16* src = (t == 3) ? Blo : Bhi;
                v = *(const uint4*)(src + (long)(bn + r) * K + k0 + s * 8);
            }
            *(uint4*)(base + t * GM_TILE + r * GM_ROWB + s * 16) = v;
        }
    };

    const int nch = K / GM_BK;
    load_stage(0, 0);
    __syncthreads();

    for (int c = 0; c < nch; c++) {
        const uint32_t st = sb + (c & 1) * GM_STAGE;
        if (c + 1 < nch) load_stage((c + 1) & 1, c + 1);
#pragma unroll
        for (int ks = 0; ks < 2; ks++) {
            const int koff = ks * 32;
            uint32_t ah[2][4], al[2][4];
#pragma unroll
            for (int mf = 0; mf < 2; mf++) {
                uint32_t ra = st + (uint32_t)((mbase + mf * 16 + a_row) * GM_ROWB + koff + a_koff);
                ldsm4(ah[mf], ra);
                ldsm4(al[mf], ra + GM_TILE);
            }
            uint32_t bh[4][4], bl[4][4];
#pragma unroll
            for (int nf = 0; nf < 4; nf++) {
                uint32_t rb = st + 2 * GM_TILE +
                              (uint32_t)((nbase + nf * 16 + b_row) * GM_ROWB + koff + b_koff);
                ldsm4(bh[nf], rb);            // NON-trans: smem is [n][k], matches B col-major fragment
                ldsm4(bl[nf], rb + GM_TILE);
            }
#pragma unroll
            for (int mf = 0; mf < 2; mf++)
#pragma unroll
                for (int nf = 0; nf < 4; nf++)
#pragma unroll
                    for (int h = 0; h < 2; h++) {
                        float* a4 = acc[mf][nf * 2 + h];
                        mma16816(a4, ah[mf], bh[nf][h * 2], bh[nf][h * 2 + 1]);
                        mma16816(a4, ah[mf], bl[nf][h * 2], bl[nf][h * 2 + 1]);
                        mma16816(a4, al[mf], bh[nf][h * 2], bh[nf][h * 2 + 1]);
                    }
        }
        __syncthreads();
    }

    // epilogue
#pragma unroll
    for (int mf = 0; mf < 2; mf++)
#pragma unroll
        for (int nf = 0; nf < 8; nf++) {
            const int row0 = bm + mbase + mf * 16 + (lane >> 2);
            const int col = bn + nbase + nf * 8 + (lane & 3) * 2;
            const float* a4 = acc[mf][nf];
#pragma unroll
            for (int half = 0; half < 2; half++) {
                int row = row0 + half * 8;
                if (row >= M) continue;
                float v0 = a4[half * 2 + 0], v1 = a4[half * 2 + 1];
                if (outmap == 1) {
                    long crow = (long)row + row / TC + 1;
                    __nv_bfloat16 h0 = __float2bfloat16(v0);
                    __nv_bfloat16 h1 = __float2bfloat16(v1);
                    Chi[crow * DD + col] = h0;
                    Chi[crow * DD + col + 1] = h1;
                    Clo[crow * DD + col] = __float2bfloat16(v0 - __bfloat162float(h0));
                    Clo[crow * DD + col + 1] = __float2bfloat16(v1 - __bfloat162float(h1));
                } else {
                    if (bias) { v0 += bias[col]; v1 += bias[col + 1]; }
                    *(float2*)(Cf + (long)row * DD + col) = make_float2(v0, v1);
                }
            }
        }
}

// ---------------- flash attention with 3k<=q mask (fp32 SIMT, bf16 hi/lo output) ----------------
#define AT_BQ 128
#define AT_BK 32
__global__ void __launch_bounds__(128, 2)
attn_kernel(const float* __restrict__ Q, const float* __restrict__ Kg,
            const float* __restrict__ Vg,
            __nv_bfloat16* __restrict__ Ohi, __nv_bfloat16* __restrict__ Olo)
{
    __shared__ float Ks[AT_BK][HD];
    __shared__ float Vs[AT_BK][HD];

    const int bh = blockIdx.y;
    const int b = bh >> 4;
    const int h = bh & 15;
    const int q0 = blockIdx.x * AT_BQ;
    const int tid = threadIdx.x;
    const int q = q0 + tid;
    const float scale = 0.125f;

    float qreg[HD];
    const float* qp = Q + ((long)(b * TT + q) * DD) + h * HD;
#pragma unroll
    for (int i = 0; i < HD; i += 4) {
        float4 v = *(const float4*)(qp + i);
        qreg[i] = v.x * scale; qreg[i + 1] = v.y * scale;
        qreg[i + 2] = v.z * scale; qreg[i + 3] = v.w * scale;
    }

    float o[HD];
#pragma unroll
    for (int i = 0; i < HD; i++) o[i] = 0.f;
    float m = -1e30f, l = 0.f;

    const int kallow = q / 3;
    const int nk = ((q0 + AT_BQ - 1) / 3) + 1;

    for (int kt = 0; kt < nk; kt += AT_BK) {
        for (int idx = tid; idx < AT_BK * (HD / 4); idx += AT_BQ) {
            int r = idx >> 4;
            int c4 = (idx & 15) * 4;
            int kid = kt + r;
            float4 kv = make_float4(0.f, 0.f, 0.f, 0.f), vv = kv;
            if (kid < TKK) {
                long off = ((long)(b * TKK + kid) * DD) + h * HD + c4;
                kv = *(const float4*)(Kg + off);
                vv = *(const float4*)(Vg + off);
            }
            *(float4*)&Ks[r][c4] = kv;
            *(float4*)&Vs[r][c4] = vv;
        }
        __syncthreads();

        float s[AT_BK];
#pragma unroll
        for (int j = 0; j < AT_BK; j++) {
            float acc = 0.f;
#pragma unroll
            for (int i = 0; i < HD; i++) acc = fmaf(qreg[i], Ks[j][i], acc);
            s[j] = acc;
        }

        float mnew = m;
#pragma unroll
        for (int j = 0; j < AT_BK; j++) {
            if (kt + j > kallow) s[j] = -1e30f;
            mnew = fmaxf(mnew, s[j]);
        }

        float corr = __expf(m - mnew);
        l *= corr;
#pragma unroll
        for (int i = 0; i < HD; i++) o[i] *= corr;

#pragma unroll
        for (int j = 0; j < AT_BK; j++) {
            float p = __expf(s[j] - mnew);
            l += p;
#pragma unroll
            for (int i = 0; i < HD; i++) o[i] = fmaf(p, Vs[j][i], o[i]);
        }
        m = mnew;
        __syncthreads();
    }

    float inv = 1.f / l;
    long obase = ((long)(b * TT + q) * DD) + h * HD;
#pragma unroll
    for (int i = 0; i < HD; i++) {
        float v = o[i] * inv;
        __nv_bfloat16 hi = __float2bfloat16(v);
        Ohi[obase + i] = hi;
        Olo[obase + i] = __float2bfloat16(v - __bfloat162float(hi));
    }
}

// ---------------- launch ----------------
extern "C" void kernel_launch(void* const* d_in, const int* in_sizes, int n_in,
                              void* d_out, int out_size)
{
    const float* x     = (const float*)d_in[0];
    const float* Wq    = (const float*)d_in[1];
    const float* Wk    = (const float*)d_in[2];
    const float* Wv    = (const float*)d_in[3];
    const float* Wo    = (const float*)d_in[4];
    const float* bo    = (const float*)d_in[5];
    const float* Wconv = (const float*)d_in[6];
    float* out = (float*)d_out;

    __nv_bfloat16 *xhi, *xlo, *wqh, *wql, *wkh, *wkl, *wvh, *wvl, *woh, *wol, *wch, *wcl;
    __nv_bfloat16 *khi, *klo, *ohi, *olo;
    float *qb, *kb, *vb;
    cudaGetSymbolAddress((void**)&xhi, g_xhi);  cudaGetSymbolAddress((void**)&xlo, g_xlo);
    cudaGetSymbolAddress((void**)&wqh, g_wqhi); cudaGetSymbolAddress((void**)&wql, g_wqlo);
    cudaGetSymbolAddress((void**)&wkh, g_wkhi); cudaGetSymbolAddress((void**)&wkl, g_wklo);
    cudaGetSymbolAddress((void**)&wvh, g_wvhi); cudaGetSymbolAddress((void**)&wvl, g_wvlo);
    cudaGetSymbolAddress((void**)&woh, g_wohi); cudaGetSymbolAddress((void**)&wol, g_wolo);
    cudaGetSymbolAddress((void**)&wch, g_wchi); cudaGetSymbolAddress((void**)&wcl, g_wclo);
    cudaGetSymbolAddress((void**)&khi, g_khi2); cudaGetSymbolAddress((void**)&klo, g_klo2);
    cudaGetSymbolAddress((void**)&ohi, g_ohi);  cudaGetSymbolAddress((void**)&olo, g_olo);
    cudaGetSymbolAddress((void**)&qb, g_q);
    cudaGetSymbolAddress((void**)&kb, g_k);
    cudaGetSymbolAddress((void**)&vb, g_v);

    cudaFuncSetAttribute(gemm_mma, cudaFuncAttributeMaxDynamicSharedMemorySize, GM_SMEM);

    // conversions
    { int n = BB * TT * DD; split_kernel<<<(n + 255) / 256, 256>>>(x, xhi, xlo, n); }
    { int n = DD * DD;
      split_kernel<<<(n + 255) / 256, 256>>>(Wq, wqh, wql, n);
      split_kernel<<<(n + 255) / 256, 256>>>(Wk, wkh, wkl, n);
      split_kernel<<<(n + 255) / 256, 256>>>(Wv, wvh, wvl, n);
      split_kernel<<<(n + 255) / 256, 256>>>(Wo, woh, wol, n); }
    { int n = DD * DD * 3; repack_conv_kernel<<<(n + 255) / 256, 256>>>(Wconv, wch, wcl); }
    { int n = BB * DD; copy_row0_kernel<<<(n + 255) / 256, 256>>>(x, khi, klo); }

    // conv GEMM -> k_tmp (scatter, bf16 hi/lo out)
    {
        dim3 grid(DD / GM_BN, (BB * TC + GM_BM - 1) / GM_BM);   // (8, 32)
        gemm_mma<<<grid, 256, GM_SMEM>>>(xhi, xlo, 3L * DD, wch, wcl, nullptr,
                                         nullptr, khi, klo, BB * TC, 3 * DD, 1);
    }
    // Q = x @ Wq^T
    {
        dim3 grid(DD / GM_BN, (BB * TT + GM_BM - 1) / GM_BM);   // (8, 96)
        gemm_mma<<<grid, 256, GM_SMEM>>>(xhi, xlo, (long)DD, wqh, wql, nullptr,
                                         qb, nullptr, nullptr, BB * TT, DD, 0);
    }
    // K, V = k_tmp @ Wk^T / Wv^T
    {
        dim3 grid(DD / GM_BN, (BB * TKK + GM_BM - 1) / GM_BM);  // (8, 33)
        gemm_mma<<<grid, 256, GM_SMEM>>>(khi, klo, (long)DD, wkh, wkl, nullptr,
                                         kb, nullptr, nullptr, BB * TKK, DD, 0);
        gemm_mma<<<grid, 256, GM_SMEM>>>(khi, klo, (long)DD, wvh, wvl, nullptr,
                                         vb, nullptr, nullptr, BB * TKK, DD, 0);
    }
    // attention
    {
        dim3 grid(TT / AT_BQ, BB * HH);                         // (24, 64)
        attn_kernel<<<grid, AT_BQ>>>(qb, kb, vb, ohi, olo);
    }
    // out = o @ Wo^T + bo
    {
        dim3 grid(DD / GM_BN, (BB * TT + GM_BM - 1) / GM_BM);   // (8, 96)
        gemm_mma<<<grid, 256, GM_SMEM>>>(ohi, olo, (long)DD, woh, wol, bo,
                                         out, nullptr, nullptr, BB * TT, DD, 0);
    }
}

// round 9
// speedup vs baseline: 2.8567x; 1.7784x over previous
#include <cuda_runtime.h>
#include <cuda_bf16.h>
#include <cstdint>
#include <math.h>

// Problem dims
#define BB 4
#define TT 3072
#define DD 1024
#define HH 16
#define HD 64
#define TC 1024          // conv outputs per batch
#define TKK 1025         // k_tmp rows per batch

// ---------------- static scratch ----------------
__device__ __nv_bfloat16 g_xhi[BB * TT * DD], g_xlo[BB * TT * DD];
__device__ __nv_bfloat16 g_wqhi[DD * DD], g_wqlo[DD * DD];
__device__ __nv_bfloat16 g_wkhi[DD * DD], g_wklo[DD * DD];
__device__ __nv_bfloat16 g_wvhi[DD * DD], g_wvlo[DD * DD];
__device__ __nv_bfloat16 g_wohi[DD * DD], g_wolo[DD * DD];
__device__ __nv_bfloat16 g_wchi[DD * 3 * DD], g_wclo[DD * 3 * DD];
__device__ __nv_bfloat16 g_khi2[BB * TKK * DD], g_klo2[BB * TKK * DD];  // k_tmp hi/lo
__device__ __nv_bfloat16 g_qhi[BB * TT * DD], g_qlo[BB * TT * DD];      // Q (pre-scaled)
__device__ __nv_bfloat16 g_kbhi[BB * TKK * DD], g_kblo[BB * TKK * DD];  // K proj
__device__ __nv_bfloat16 g_vbhi[BB * TKK * DD], g_vblo[BB * TKK * DD];  // V proj
__device__ __nv_bfloat16 g_ohi[BB * TT * DD], g_olo[BB * TT * DD];      // attn out

// ---------------- helpers ----------------
__device__ __forceinline__ uint32_t smem_u32(const void* p) {
    uint32_t a;
    asm("{ .reg .u64 t; cvta.to.shared.u64 t, %1; cvt.u32.u64 %0, t; }" : "=r"(a) : "l"(p));
    return a;
}
__device__ __forceinline__ void ldsm4(uint32_t* r, uint32_t addr) {
    asm volatile("ldmatrix.sync.aligned.m8n8.x4.shared.b16 {%0,%1,%2,%3}, [%4];"
        : "=r"(r[0]), "=r"(r[1]), "=r"(r[2]), "=r"(r[3]) : "r"(addr));
}
__device__ __forceinline__ void ldsm4t(uint32_t* r, uint32_t addr) {
    asm volatile("ldmatrix.sync.aligned.m8n8.x4.trans.shared.b16 {%0,%1,%2,%3}, [%4];"
        : "=r"(r[0]), "=r"(r[1]), "=r"(r[2]), "=r"(r[3]) : "r"(addr));
}
__device__ __forceinline__ void mma16816(float* c, const uint32_t* a, uint32_t b0, uint32_t b1) {
    asm volatile("mma.sync.aligned.m16n8k16.row.col.f32.bf16.bf16.f32 "
        "{%0,%1,%2,%3}, {%4,%5,%6,%7}, {%8,%9}, {%0,%1,%2,%3};"
        : "+f"(c[0]), "+f"(c[1]), "+f"(c[2]), "+f"(c[3])
        : "r"(a[0]), "r"(a[1]), "r"(a[2]), "r"(a[3]), "r"(b0), "r"(b1));
}
__device__ __forceinline__ uint32_t packbf2(float x, float y) {
    uint32_t lo = __bfloat16_as_ushort(__float2bfloat16(x));
    uint32_t hi = __bfloat16_as_ushort(__float2bfloat16(y));
    return lo | (hi << 16);
}

// ---------------- split / repack kernels ----------------
__global__ void split_kernel(const float* __restrict__ s, __nv_bfloat16* __restrict__ hi,
                             __nv_bfloat16* __restrict__ lo, int n) {
    int i = blockIdx.x * 256 + threadIdx.x;
    if (i >= n) return;
    float v = s[i];
    __nv_bfloat16 h = __float2bfloat16(v);
    hi[i] = h;
    lo[i] = __float2bfloat16(v - __bfloat162float(h));
}
__global__ void repack_conv_kernel(const float* __restrict__ W, __nv_bfloat16* __restrict__ hi,
                                   __nv_bfloat16* __restrict__ lo) {
    int idx = blockIdx.x * 256 + threadIdx.x;
    if (idx >= DD * DD * 3) return;
    int o = idx / (DD * 3);
    int r = idx % (DD * 3);
    int i = r / 3, kw = r % 3;
    float v = W[idx];
    __nv_bfloat16 h = __float2bfloat16(v);
    long d = (long)o * (3 * DD) + kw * DD + i;
    hi[d] = h;
    lo[d] = __float2bfloat16(v - __bfloat162float(h));
}
__global__ void copy_row0_kernel(const float* __restrict__ x, __nv_bfloat16* __restrict__ khi,
                                 __nv_bfloat16* __restrict__ klo) {
    int idx = blockIdx.x * 256 + threadIdx.x;
    if (idx >= BB * DD) return;
    int b = idx / DD, i = idx % DD;
    float v = x[(long)b * TT * DD + i];
    __nv_bfloat16 h = __float2bfloat16(v);
    long d = (long)b * TKK * DD + i;
    khi[d] = h;
    klo[d] = __float2bfloat16(v - __bfloat162float(h));
}

// ---------------- mma.sync GEMM: C[M,1024] = A @ B^T (bf16x3 split) ----------------
// outmap 0: fp32 Cf (+bias).  outmap 1: conv scatter -> bf16 hi/lo.  outmap 2: bf16 hi/lo (scaled).
#define GM_BM 128
#define GM_BN 128
#define GM_BK 32
#define GM_ROWB 80
#define GM_TILE (128 * GM_ROWB)        // 10240
#define GM_STAGE (4 * GM_TILE)         // 40960
#define GM_SMEM (2 * GM_STAGE)         // 81920

__global__ void __launch_bounds__(256)
gemm_mma(const __nv_bfloat16* __restrict__ Ahi, const __nv_bfloat16* __restrict__ Alo, long lda,
         const __nv_bfloat16* __restrict__ Bhi, const __nv_bfloat16* __restrict__ Blo,
         const float* __restrict__ bias,
         float* __restrict__ Cf, __nv_bfloat16* __restrict__ Chi, __nv_bfloat16* __restrict__ Clo,
         int M, int K, int outmap, float oscale)
{
    extern __shared__ char smem[];
    const uint32_t sb = smem_u32(smem);
    const int tid = threadIdx.x;
    const int wid = tid >> 5, lane = tid & 31;
    const int bm = blockIdx.y * GM_BM, bn = blockIdx.x * GM_BN;
    const int mbase = (wid & 3) * 32;
    const int nbase = (wid >> 2) * 64;

    const int grp = lane >> 3, rowg = lane & 7;
    const int a_row = (grp & 1) * 8 + rowg;
    const int a_koff = (grp >> 1) * 16;
    const int b_row = (grp >> 1) * 8 + rowg;
    const int b_koff = (grp & 1) * 16;

    float acc[2][8][4];
#pragma unroll
    for (int i = 0; i < 2; i++)
#pragma unroll
        for (int j = 0; j < 8; j++)
#pragma unroll
            for (int k = 0; k < 4; k++) acc[i][j][k] = 0.f;

    auto load_stage = [&](int stg, int c) {
        char* base = smem + stg * GM_STAGE;
        const int k0 = c * GM_BK;
#pragma unroll
        for (int it = 0; it < 8; it++) {
            int i = it * 256 + tid;
            int t = i >> 9;               // 0 Ahi, 1 Alo, 2 Bhi, 3 Blo
            int r = (i >> 2) & 127;
            int s = i & 3;
            uint4 v = make_uint4(0, 0, 0, 0);
            if (t < 2) {
                int row = bm + r;
                if (row < M) {
                    const __nv_bfloat16* src = t ? Alo : Ahi;
                    v = *(const uint4*)(src + (long)row * lda + k0 + s * 8);
                }
            } else {
                const __nv_bfloat16* src = (t == 3) ? Blo : Bhi;
                v = *(const uint4*)(src + (long)(bn + r) * K + k0 + s * 8);
            }
            *(uint4*)(base + t * GM_TILE + r * GM_ROWB + s * 16) = v;
        }
    };

    const int nch = K / GM_BK;
    load_stage(0, 0);
    __syncthreads();

    for (int c = 0; c < nch; c++) {
        const uint32_t st = sb + (c & 1) * GM_STAGE;
        if (c + 1 < nch) load_stage((c + 1) & 1, c + 1);
#pragma unroll
        for (int ks = 0; ks < 2; ks++) {
            const int koff = ks * 32;
            uint32_t ah[2][4], al[2][4];
#pragma unroll
            for (int mf = 0; mf < 2; mf++) {
                uint32_t ra = st + (uint32_t)((mbase + mf * 16 + a_row) * GM_ROWB + koff + a_koff);
                ldsm4(ah[mf], ra);
                ldsm4(al[mf], ra + GM_TILE);
            }
            uint32_t bh[4][4], bl[4][4];
#pragma unroll
            for (int nf = 0; nf < 4; nf++) {
                uint32_t rb = st + 2 * GM_TILE +
                              (uint32_t)((nbase + nf * 16 + b_row) * GM_ROWB + koff + b_koff);
                ldsm4(bh[nf], rb);
                ldsm4(bl[nf], rb + GM_TILE);
            }
#pragma unroll
            for (int mf = 0; mf < 2; mf++)
#pragma unroll
                for (int nf = 0; nf < 4; nf++)
#pragma unroll
                    for (int h = 0; h < 2; h++) {
                        float* a4 = acc[mf][nf * 2 + h];
                        mma16816(a4, ah[mf], bh[nf][h * 2], bh[nf][h * 2 + 1]);
                        mma16816(a4, ah[mf], bl[nf][h * 2], bl[nf][h * 2 + 1]);
                        mma16816(a4, al[mf], bh[nf][h * 2], bh[nf][h * 2 + 1]);
                    }
        }
        __syncthreads();
    }

    // epilogue
#pragma unroll
    for (int mf = 0; mf < 2; mf++)
#pragma unroll
        for (int nf = 0; nf < 8; nf++) {
            const int row0 = bm + mbase + mf * 16 + (lane >> 2);
            const int col = bn + nbase + nf * 8 + (lane & 3) * 2;
            const float* a4 = acc[mf][nf];
#pragma unroll
            for (int half = 0; half < 2; half++) {
                int row = row0 + half * 8;
                if (row >= M) continue;
                float v0 = a4[half * 2 + 0], v1 = a4[half * 2 + 1];
                if (outmap == 1) {
                    long crow = (long)row + row / TC + 1;
                    __nv_bfloat16 h0 = __float2bfloat16(v0);
                    __nv_bfloat16 h1 = __float2bfloat16(v1);
                    Chi[crow * DD + col] = h0;
                    Chi[crow * DD + col + 1] = h1;
                    Clo[crow * DD + col] = __float2bfloat16(v0 - __bfloat162float(h0));
                    Clo[crow * DD + col + 1] = __float2bfloat16(v1 - __bfloat162float(h1));
                } else if (outmap == 2) {
                    v0 *= oscale; v1 *= oscale;
                    __nv_bfloat16 h0 = __float2bfloat16(v0);
                    __nv_bfloat16 h1 = __float2bfloat16(v1);
                    Chi[(long)row * DD + col] = h0;
                    Chi[(long)row * DD + col + 1] = h1;
                    Clo[(long)row * DD + col] = __float2bfloat16(v0 - __bfloat162float(h0));
                    Clo[(long)row * DD + col + 1] = __float2bfloat16(v1 - __bfloat162float(h1));
                } else {
                    if (bias) { v0 += bias[col]; v1 += bias[col + 1]; }
                    *(float2*)(Cf + (long)row * DD + col) = make_float2(v0, v1);
                }
            }
        }
}

// ---------------- mma.sync flash attention, 3k<=q mask ----------------
// 128 queries/CTA (8 warps x 16 rows), 64-key tiles, cp.async double buffer.
#define FA_BQ 128
#define FA_BK 64
#define FA_ROWB 144
#define FA_TILE (64 * FA_ROWB)     // 9216
#define FA_STAGE (4 * FA_TILE)     // 36864 : Khi, Klo, Vhi, Vlo
#define FA_SMEM (2 * FA_STAGE)     // 73728

__global__ void __launch_bounds__(256)
attn_mma(const __nv_bfloat16* __restrict__ Qhi, const __nv_bfloat16* __restrict__ Qlo,
         const __nv_bfloat16* __restrict__ Khi, const __nv_bfloat16* __restrict__ Klo,
         const __nv_bfloat16* __restrict__ Vhi, const __nv_bfloat16* __restrict__ Vlo,
         __nv_bfloat16* __restrict__ Ohi, __nv_bfloat16* __restrict__ Olo)
{
    extern __shared__ char smem[];
    const uint32_t sb = smem_u32(smem);
    const int tid = threadIdx.x, wid = tid >> 5, lane = tid & 31;
    const int bh = blockIdx.y, b = bh >> 4, h = bh & 15;
    const int q0 = blockIdx.x * FA_BQ;

    const int grp = lane >> 3, rowg = lane & 7;
    const int a_row = (grp & 1) * 8 + rowg, a_koff = (grp >> 1) * 16;
    const int b_row = (grp >> 1) * 8 + rowg, b_koff = (grp & 1) * 16;
    const int v_row = (grp & 1) * 8 + rowg, v_koff = (grp >> 1) * 16;
    const int lq = lane >> 2, lc = (lane & 3) * 2;
    const int qrow0 = q0 + wid * 16 + lq;
    const int qrow1 = qrow0 + 8;

    // ---- stage Q (hi at 0, lo at +18432), extract fragments ----
#pragma unroll
    for (int it = 0; it < 8; it++) {
        int idx = it * 256 + tid;
        int t = idx >> 10, r = (idx >> 3) & 127, s = idx & 7;
        const __nv_bfloat16* src = t ? Qlo : Qhi;
        uint4 v = *(const uint4*)(src + (long)(b * TT + q0 + r) * DD + h * HD + s * 8);
        *(uint4*)(smem + t * 18432 + r * FA_ROWB + s * 16) = v;
    }
    __syncthreads();
    uint32_t qh[4][4], ql[4][4];
#pragma unroll
    for (int ks = 0; ks < 4; ks++) {
        uint32_t ra = sb + (uint32_t)((wid * 16 + a_row) * FA_ROWB + ks * 32 + a_koff);
        ldsm4(qh[ks], ra);
        ldsm4(ql[ks], ra + 18432);
    }
    __syncthreads();

    const int kmax = (q0 + FA_BQ - 1) / 3;
    const int nt = kmax / FA_BK + 1;

    auto load_kv = [&](int stg, int t) {
        const int kt = t * FA_BK;
        const uint32_t dst0 = sb + stg * FA_STAGE;
#pragma unroll
        for (int it = 0; it < 8; it++) {
            int idx = it * 256 + tid;
            int tt = idx >> 9, r = (idx >> 3) & 63, s = idx & 7;
            int kid = kt + r;
            if (kid > TKK - 1) kid = TKK - 1;
            const __nv_bfloat16* src = (tt == 0) ? Khi : (tt == 1) ? Klo : (tt == 2) ? Vhi : Vlo;
            const __nv_bfloat16* sp = src + (long)(b * TKK + kid) * DD + h * HD + s * 8;
            uint32_t dp = dst0 + (uint32_t)(tt * FA_TILE + r * FA_ROWB + s * 16);
            asm volatile("cp.async.cg.shared.global [%0], [%1], 16;" :: "r"(dp), "l"(sp));
        }
        asm volatile("cp.async.commit_group;" ::: "memory");
    };

    float Oa[8][4];
#pragma unroll
    for (int i = 0; i < 8; i++)
#pragma unroll
        for (int j = 0; j < 4; j++) Oa[i][j] = 0.f;
    float m0 = -1e30f, m1 = -1e30f, l0 = 0.f, l1 = 0.f;

    load_kv(0, 0);

    for (int t = 0; t < nt; t++) {
        const int stg = t & 1;
        if (t + 1 < nt) {
            load_kv(stg ^ 1, t + 1);
            asm volatile("cp.async.wait_group 1;" ::: "memory");
        } else {
            asm volatile("cp.async.wait_group 0;" ::: "memory");
        }
        __syncthreads();

        const int kt = t * FA_BK;
        const uint32_t stk = sb + stg * FA_STAGE;
        const uint32_t stv = stk + 2 * FA_TILE;

        // ---- S = Qs @ K^T (split) ----
        float S[8][4];
#pragma unroll
        for (int i = 0; i < 8; i++)
#pragma unroll
            for (int j = 0; j < 4; j++) S[i][j] = 0.f;

#pragma unroll
        for (int ng = 0; ng < 4; ng++) {
#pragma unroll
            for (int ks = 0; ks < 4; ks++) {
                uint32_t kh[4], kl[4];
                uint32_t rb = stk + (uint32_t)((ng * 16 + b_row) * FA_ROWB + ks * 32 + b_koff);
                ldsm4(kh, rb);
                ldsm4(kl, rb + FA_TILE);
                mma16816(S[2 * ng],     qh[ks], kh[0], kh[1]);
                mma16816(S[2 * ng + 1], qh[ks], kh[2], kh[3]);
                mma16816(S[2 * ng],     qh[ks], kl[0], kl[1]);
                mma16816(S[2 * ng + 1], qh[ks], kl[2], kl[3]);
                mma16816(S[2 * ng],     ql[ks], kh[0], kh[1]);
                mma16816(S[2 * ng + 1], ql[ks], kh[2], kh[3]);
            }
        }

        // ---- mask + online softmax ----
        float mx0 = -1e30f, mx1 = -1e30f;
#pragma unroll
        for (int nf = 0; nf < 8; nf++) {
            int key = kt + nf * 8 + lc;
            if (3 * key > qrow0)       S[nf][0] = -1e30f;
            if (3 * (key + 1) > qrow0) S[nf][1] = -1e30f;
            if (3 * key > qrow1)       S[nf][2] = -1e30f;
            if (3 * (key + 1) > qrow1) S[nf][3] = -1e30f;
            mx0 = fmaxf(mx0, fmaxf(S[nf][0], S[nf][1]));
            mx1 = fmaxf(mx1, fmaxf(S[nf][2], S[nf][3]));
        }
        mx0 = fmaxf(mx0, __shfl_xor_sync(0xFFFFFFFF, mx0, 1));
        mx0 = fmaxf(mx0, __shfl_xor_sync(0xFFFFFFFF, mx0, 2));
        mx1 = fmaxf(mx1, __shfl_xor_sync(0xFFFFFFFF, mx1, 1));
        mx1 = fmaxf(mx1, __shfl_xor_sync(0xFFFFFFFF, mx1, 2));
        float mn0 = fmaxf(m0, mx0), mn1 = fmaxf(m1, mx1);
        float c0 = __expf(m0 - mn0), c1 = __expf(m1 - mn1);

        float ls0 = 0.f, ls1 = 0.f;
#pragma unroll
        for (int nf = 0; nf < 8; nf++) {
            S[nf][0] = __expf(S[nf][0] - mn0);
            S[nf][1] = __expf(S[nf][1] - mn0);
            S[nf][2] = __expf(S[nf][2] - mn1);
            S[nf][3] = __expf(S[nf][3] - mn1);
            ls0 += S[nf][0] + S[nf][1];
            ls1 += S[nf][2] + S[nf][3];
        }
        ls0 += __shfl_xor_sync(0xFFFFFFFF, ls0, 1);
        ls0 += __shfl_xor_sync(0xFFFFFFFF, ls0, 2);
        ls1 += __shfl_xor_sync(0xFFFFFFFF, ls1, 1);
        ls1 += __shfl_xor_sync(0xFFFFFFFF, ls1, 2);
        l0 = l0 * c0 + ls0;
        l1 = l1 * c1 + ls1;
        m0 = mn0; m1 = mn1;

#pragma unroll
        for (int nf = 0; nf < 8; nf++) {
            Oa[nf][0] *= c0; Oa[nf][1] *= c0;
            Oa[nf][2] *= c1; Oa[nf][3] *= c1;
        }

        // ---- O += P @ V (P split hi/lo, V split hi/lo) ----
#pragma unroll
        for (int g = 0; g < 4; g++) {
            uint32_t ph[4], pl[4];
            float p00 = S[2 * g][0], p01 = S[2 * g][1], p02 = S[2 * g][2], p03 = S[2 * g][3];
            float p10 = S[2 * g + 1][0], p11 = S[2 * g + 1][1], p12 = S[2 * g + 1][2], p13 = S[2 * g + 1][3];
            ph[0] = packbf2(p00, p01); ph[1] = packbf2(p02, p03);
            ph[2] = packbf2(p10, p11); ph[3] = packbf2(p12, p13);
            float r00 = p00 - __bfloat162float(__float2bfloat16(p00));
            float r01 = p01 - __bfloat162float(__float2bfloat16(p01));
            float r02 = p02 - __bfloat162float(__float2bfloat16(p02));
            float r03 = p03 - __bfloat162float(__float2bfloat16(p03));
            float r10 = p10 - __bfloat162float(__float2bfloat16(p10));
            float r11 = p11 - __bfloat162float(__float2bfloat16(p11));
            float r12 = p12 - __bfloat162float(__float2bfloat16(p12));
            float r13 = p13 - __bfloat162float(__float2bfloat16(p13));
            pl[0] = packbf2(r00, r01); pl[1] = packbf2(r02, r03);
            pl[2] = packbf2(r10, r11); pl[3] = packbf2(r12, r13);
#pragma unroll
            for (int dg = 0; dg < 4; dg++) {
                uint32_t vh[4], vl[4];
                uint32_t rv = stv + (uint32_t)((g * 16 + v_row) * FA_ROWB + dg * 32 + v_koff);
                ldsm4t(vh, rv);
                ldsm4t(vl, rv + FA_TILE);
                mma16816(Oa[2 * dg],     ph, vh[0], vh[1]);
                mma16816(Oa[2 * dg + 1], ph, vh[2], vh[3]);
                mma16816(Oa[2 * dg],     ph, vl[0], vl[1]);
                mma16816(Oa[2 * dg + 1], ph, vl[2], vl[3]);
                mma16816(Oa[2 * dg],     pl, vh[0], vh[1]);
                mma16816(Oa[2 * dg + 1], pl, vh[2], vh[3]);
            }
        }
        __syncthreads();
    }

    // ---- normalize + store bf16 hi/lo ----
    const float inv0 = 1.f / l0, inv1 = 1.f / l1;
#pragma unroll
    for (int nf = 0; nf < 8; nf++) {
#pragma unroll
        for (int r = 0; r < 2; r++) {
            int row = (r == 0) ? qrow0 : qrow1;
            float inv = (r == 0) ? inv0 : inv1;
            float v0 = Oa[nf][r * 2 + 0] * inv;
            float v1 = Oa[nf][r * 2 + 1] * inv;
            long base = (long)(b * TT + row) * DD + h * HD + nf * 8 + lc;
            __nv_bfloat16 h0 = __float2bfloat16(v0);
            __nv_bfloat16 h1 = __float2bfloat16(v1);
            *(uint32_t*)(Ohi + base) =
                (uint32_t)__bfloat16_as_ushort(h0) | ((uint32_t)__bfloat16_as_ushort(h1) << 16);
            __nv_bfloat16 e0 = __float2bfloat16(v0 - __bfloat162float(h0));
            __nv_bfloat16 e1 = __float2bfloat16(v1 - __bfloat162float(h1));
            *(uint32_t*)(Olo + base) =
                (uint32_t)__bfloat16_as_ushort(e0) | ((uint32_t)__bfloat16_as_ushort(e1) << 16);
        }
    }
}

// ---------------- launch ----------------
extern "C" void kernel_launch(void* const* d_in, const int* in_sizes, int n_in,
                              void* d_out, int out_size)
{
    const float* x     = (const float*)d_in[0];
    const float* Wq    = (const float*)d_in[1];
    const float* Wk    = (const float*)d_in[2];
    const float* Wv    = (const float*)d_in[3];
    const float* Wo    = (const float*)d_in[4];
    const float* bo    = (const float*)d_in[5];
    const float* Wconv = (const float*)d_in[6];
    float* out = (float*)d_out;

    __nv_bfloat16 *xhi, *xlo, *wqh, *wql, *wkh, *wkl, *wvh, *wvl, *woh, *wol, *wch, *wcl;
    __nv_bfloat16 *khi, *klo, *qhi, *qlo, *kbh, *kbl, *vbh, *vbl, *ohi, *olo;
    cudaGetSymbolAddress((void**)&xhi, g_xhi);  cudaGetSymbolAddress((void**)&xlo, g_xlo);
    cudaGetSymbolAddress((void**)&wqh, g_wqhi); cudaGetSymbolAddress((void**)&wql, g_wqlo);
    cudaGetSymbolAddress((void**)&wkh, g_wkhi); cudaGetSymbolAddress((void**)&wkl, g_wklo);
    cudaGetSymbolAddress((void**)&wvh, g_wvhi); cudaGetSymbolAddress((void**)&wvl, g_wvlo);
    cudaGetSymbolAddress((void**)&woh, g_wohi); cudaGetSymbolAddress((void**)&wol, g_wolo);
    cudaGetSymbolAddress((void**)&wch, g_wchi); cudaGetSymbolAddress((void**)&wcl, g_wclo);
    cudaGetSymbolAddress((void**)&khi, g_khi2); cudaGetSymbolAddress((void**)&klo, g_klo2);
    cudaGetSymbolAddress((void**)&qhi, g_qhi);  cudaGetSymbolAddress((void**)&qlo, g_qlo);
    cudaGetSymbolAddress((void**)&kbh, g_kbhi); cudaGetSymbolAddress((void**)&kbl, g_kblo);
    cudaGetSymbolAddress((void**)&vbh, g_vbhi); cudaGetSymbolAddress((void**)&vbl, g_vblo);
    cudaGetSymbolAddress((void**)&ohi, g_ohi);  cudaGetSymbolAddress((void**)&olo, g_olo);

    cudaFuncSetAttribute(gemm_mma, cudaFuncAttributeMaxDynamicSharedMemorySize, GM_SMEM);
    cudaFuncSetAttribute(attn_mma, cudaFuncAttributeMaxDynamicSharedMemorySize, FA_SMEM);

    // conversions
    { int n = BB * TT * DD; split_kernel<<<(n + 255) / 256, 256>>>(x, xhi, xlo, n); }
    { int n = DD * DD;
      split_kernel<<<(n + 255) / 256, 256>>>(Wq, wqh, wql, n);
      split_kernel<<<(n + 255) / 256, 256>>>(Wk, wkh, wkl, n);
      split_kernel<<<(n + 255) / 256, 256>>>(Wv, wvh, wvl, n);
      split_kernel<<<(n + 255) / 256, 256>>>(Wo, woh, wol, n); }
    { int n = DD * DD * 3; repack_conv_kernel<<<(n + 255) / 256, 256>>>(Wconv, wch, wcl); }
    { int n = BB * DD; copy_row0_kernel<<<(n + 255) / 256, 256>>>(x, khi, klo); }

    // conv GEMM -> k_tmp (scatter, bf16 hi/lo out)
    {
        dim3 grid(DD / GM_BN, (BB * TC + GM_BM - 1) / GM_BM);
        gemm_mma<<<grid, 256, GM_SMEM>>>(xhi, xlo, 3L * DD, wch, wcl, nullptr,
                                         nullptr, khi, klo, BB * TC, 3 * DD, 1, 1.f);
    }
    // Q = (x @ Wq^T) * 0.125 -> bf16 hi/lo
    {
        dim3 grid(DD / GM_BN, (BB * TT + GM_BM - 1) / GM_BM);
        gemm_mma<<<grid, 256, GM_SMEM>>>(xhi, xlo, (long)DD, wqh, wql, nullptr,
                                         nullptr, qhi, qlo, BB * TT, DD, 2, 0.125f);
    }
    // K, V = k_tmp @ Wk^T / Wv^T -> bf16 hi/lo
    {
        dim3 grid(DD / GM_BN, (BB * TKK + GM_BM - 1) / GM_BM);
        gemm_mma<<<grid, 256, GM_SMEM>>>(khi, klo, (long)DD, wkh, wkl, nullptr,
                                         nullptr, kbh, kbl, BB * TKK, DD, 2, 1.f);
        gemm_mma<<<grid, 256, GM_SMEM>>>(khi, klo, (long)DD, wvh, wvl, nullptr,
                                         nullptr, vbh, vbl, BB * TKK, DD, 2, 1.f);
    }
    // attention (tensor-core)
    {
        dim3 grid(TT / FA_BQ, BB * HH);                        // (24, 64)
        attn_mma<<<grid, 256, FA_SMEM>>>(qhi, qlo, kbh, kbl, vbh, vbl, ohi, olo);
    }
    // out = o @ Wo^T + bo
    {
        dim3 grid(DD / GM_BN, (BB * TT + GM_BM - 1) / GM_BM);
        gemm_mma<<<grid, 256, GM_SMEM>>>(ohi, olo, (long)DD, woh, wol, bo,
                                         out, nullptr, nullptr, BB * TT, DD, 0, 1.f);
    }
}